// round 10
// baseline (speedup 1.0000x reference)
#include <cuda_runtime.h>

#define NV 23
#define NN 529          // 23*23
#define TV 12
#define ROWLEN 6348     // N*N*T floats per batch
#define MSTRIDE (NV*TV) // 276 floats between consecutive m at fixed i
#define NI 6            // i-values per group (last group has 5)
#define NGROUPS 4
#define NTHREADS 160    // 5 warps; active = NI*23 = 138 (or 115 in last group)
#define GX 296          // batch-parallel blocks per group -> 296*4 = 1184 blocks (8/SM)
#define CHUNK 4         // batches per barrier

__global__ __launch_bounds__(NTHREADS, 8)
void gat_kernel(const float* __restrict__ flow,
                const int*   __restrict__ adj,
                const float* __restrict__ W,
                float*       __restrict__ out,
                int B)
{
    __shared__ float dbuf[2][CHUNK][NI * NV];   // staged d[i_local][m] slices

    const int tid   = threadIdx.x;
    const int gbase = blockIdx.y * NI;                 // first i of this group
    const int ni    = (blockIdx.y == NGROUPS - 1) ? (NV - gbase) : NI;
    const int nact  = ni * NV;                         // active thread count
    const bool act  = (tid < nact);

    // compute role: (i_local, k);  load role: (i_load = tid/23, m_load = tid%23)
    int il = 0, k = 0;
    if (act) { il = tid / NV; k = tid - il * NV; }
    const int i = gbase + il;

    // ---- per-thread attention row att[i][k][0..22] in registers ----
    float att[NV];
    if (act) {
        const float* wr = W + (i * NV + k) * NV;
        const int*   ar = adj + k * NV;
        float mn = 0.0f;                               // = min(min_m W, 0)
        #pragma unroll
        for (int m = 0; m < NV; ++m) {
            att[m] = wr[m];
            mn = fminf(mn, att[m]);
        }
        float s = 0.0f;
        #pragma unroll
        for (int m = 0; m < NV; ++m) {
            int a = (k == m) ? 1 : __ldg(ar + m);      // forced self-loop
            float v = (a != 0) ? (att[m] - mn) : 0.0f;
            att[m] = v;
            s += v;
        }
        float inv = 1.0f / s;
        #pragma unroll
        for (int m = 0; m < NV; ++m) att[m] *= inv;
    }

    // ---- gather pointer for the load role ----
    const int m_ld = act ? (tid % NV) : 0;
    const int i_ld = act ? (tid / NV) : 0;
    const float* gsrc = flow + m_ld * MSTRIDE + (gbase + i_ld) * TV + (TV - 1);

    const float* dslice = &dbuf[0][0][il * NV];        // this thread's 23-elem row
    float* obase = out + (size_t)(i * NV + k);

    // ---- chunked batch loop, double-buffered, 5-warp barrier per CHUNK ----
    const int step = GX * CHUNK;
    int base = blockIdx.x * CHUNK;

    // prologue: stage first chunk
    if (act) {
        #pragma unroll
        for (int c = 0; c < CHUNK; ++c) {
            const int b = base + c;
            dbuf[0][c][tid] = (b < B) ? __ldg(gsrc + (size_t)b * ROWLEN) : 0.0f;
        }
    }
    __syncthreads();

    int p = 0;
    for (; base < B; base += step) {
        const int nbase = base + step;

        // 1) prefetch next chunk FIRST (loads enter memory system at period start)
        float nv[CHUNK];
        if (act) {
            #pragma unroll
            for (int c = 0; c < CHUNK; ++c) {
                const int b = nbase + c;
                nv[c] = (b < B) ? __ldg(gsrc + (size_t)b * ROWLEN) : 0.0f;
            }
        }

        // 2) compute CHUNK outputs from staged buffers (hides prefetch latency)
        if (act) {
            #pragma unroll
            for (int c = 0; c < CHUNK; ++c) {
                const int b = base + c;
                if (b < B) {
                    const float* d = dslice + (size_t)(p * CHUNK + c) * (NI * NV);
                    float acc = 0.0f;
                    #pragma unroll
                    for (int m = 0; m < NV; ++m)
                        acc = fmaf(att[m], d[m], acc);
                    obase[(size_t)b * NN] = acc;
                }
            }
        }

        // 3) land prefetched chunk into the other buffer
        if (act) {
            #pragma unroll
            for (int c = 0; c < CHUNK; ++c)
                dbuf[p ^ 1][c][tid] = nv[c];
        }
        __syncthreads();
        p ^= 1;
    }
}

extern "C" void kernel_launch(void* const* d_in, const int* in_sizes, int n_in,
                              void* d_out, int out_size) {
    const float* flow = (const float*)d_in[0];   // (B, N, N, T) fp32
    const int*   adj  = (const int*)  d_in[1];   // (N, N) int32
    const float* W    = (const float*)d_in[2];   // (N, N, N) fp32
    float*       out  = (float*)d_out;           // (B, N, N, 1) fp32

    const int B = in_sizes[0] / ROWLEN;
    dim3 grid(GX, NGROUPS);
    gat_kernel<<<grid, NTHREADS>>>(flow, adj, W, out, B);
}

// round 12
// speedup vs baseline: 1.0231x; 1.0231x over previous
#include <cuda_runtime.h>
#include <cstdint>

#define NV 23
#define NN 529              // 23*23
#define TV 12
#define ROWLEN 6348         // N*N*T floats per batch row
#define ROWBYTES 25392      // = ROWLEN*4, multiple of 16
#define NSTAGES 4
#define NTHREADS 544        // 17 warps; 529 active
#define NBLOCKS 296         // 2 CTAs per SM

// dynamic smem layout (float index):
//   [0..7]    : 4 mbarriers (u64, 8B each -> 32B)
//   [8..536]  : dc[529] compact extracted slice
//   [540..]   : ring[NSTAGES][ROWLEN]  (byte offset 2160, 16B aligned)
#define DC_OFF   8
#define RING_OFF 540
#define SMEM_BYTES (RING_OFF * 4 + NSTAGES * ROWBYTES)   // 2160 + 101568 = 103728

__global__ __launch_bounds__(NTHREADS)
void gat_kernel(const float* __restrict__ flow,
                const int*   __restrict__ adj,
                const float* __restrict__ W,
                float*       __restrict__ out,
                int B)
{
    extern __shared__ float smem[];
    const uint32_t sbase = (uint32_t)__cvta_generic_to_shared(smem);
    const uint32_t mbar0 = sbase;                       // 4 x 8B barriers
    float* dc   = smem + DC_OFF;                        // [529]
    float* ring = smem + RING_OFF;
    const uint32_t ring_a = sbase + RING_OFF * 4u;

    const int tid  = threadIdx.x;
    const bool act = (tid < NN);

    const int blk = blockIdx.x;
    const int nit = (B - blk + NBLOCKS - 1) / NBLOCKS;  // rows this block handles

    // ---- mbarrier init (count=1: the expect_tx arrive) ----
    if (tid == 0) {
        #pragma unroll
        for (int s = 0; s < NSTAGES; ++s)
            asm volatile("mbarrier.init.shared.b64 [%0], %1;"
                         :: "r"(mbar0 + s * 8u), "r"(1u) : "memory");
    }
    __syncthreads();

    // ---- issue helper: bulk-copy one batch row into ring stage (tid 0 only) ----
    auto issue = [&](int it) {
        const int r = blk + it * NBLOCKS;
        if (r >= B) return;
        const int s = it & (NSTAGES - 1);
        const uint32_t mb  = mbar0 + s * 8u;
        const uint32_t dst = ring_a + (uint32_t)s * ROWBYTES;
        const float* src = flow + (size_t)r * ROWLEN;
        asm volatile("mbarrier.arrive.expect_tx.shared.b64 _, [%0], %1;"
                     :: "r"(mb), "r"((uint32_t)ROWBYTES) : "memory");
        asm volatile("cp.async.bulk.shared::cluster.global.mbarrier::complete_tx::bytes "
                     "[%0], [%1], %2, [%3];"
                     :: "r"(dst), "l"(src), "r"((uint32_t)ROWBYTES), "r"(mb) : "memory");
    };

    // ---- prologue: fill 3 stages immediately, then attention math overlaps TMA ----
    if (tid == 0) { issue(0); issue(1); issue(2); }

    float att[NV];
    if (act) {
        const int k = tid % NV;                         // tid = i*23 + k
        const float* wr = W + tid * NV;
        const int*   ar = adj + k * NV;
        float mn = 0.0f;                                // = min(min_m W, 0)
        #pragma unroll
        for (int m = 0; m < NV; ++m) {
            att[m] = wr[m];
            mn = fminf(mn, att[m]);
        }
        float s = 0.0f;
        #pragma unroll
        for (int m = 0; m < NV; ++m) {
            int a = (k == m) ? 1 : __ldg(ar + m);       // forced self-loop
            float v = (a != 0) ? (att[m] - mn) : 0.0f;
            att[m] = v;
            s += v;
        }
        float inv = 1.0f / s;
        #pragma unroll
        for (int m = 0; m < NV; ++m) att[m] *= inv;
    }
    const int il = act ? (tid / NV) : 0;                // i index for compute reads

    // ---- main pipeline: wait stage -> extract -> compute -> refill ----
    for (int it = 0; it < nit; ++it) {
        // refill slot (it+3): its previous occupant was consumed in iter it-1
        if (tid == 0) {
            asm volatile("fence.proxy.async.shared::cta;" ::: "memory");
            issue(it + NSTAGES - 1);
        }

        const int s  = it & (NSTAGES - 1);
        const int ph = (it >> 2) & 1;
        const uint32_t mb = mbar0 + s * 8u;

        // wait stage full (acquire)
        {
            uint32_t done = 0;
            while (!done) {
                asm volatile(
                    "{\n\t.reg .pred p;\n\t"
                    "mbarrier.try_wait.parity.acquire.cta.shared::cta.b64 p, [%1], %2, 0x989680;\n\t"
                    "selp.b32 %0, 1, 0, p;\n\t}"
                    : "=r"(done) : "r"(mb), "r"((uint32_t)ph) : "memory");
            }
        }

        // extract the 529 wanted floats -> compact dc
        const float* rs = ring + (size_t)s * ROWLEN;
        if (act)
            dc[tid] = rs[tid * TV + (TV - 1)];
        __syncthreads();

        // compute + coalesced store
        const int r = blk + it * NBLOCKS;
        if (act) {
            float acc = 0.0f;
            #pragma unroll
            for (int m = 0; m < NV; ++m)
                acc = fmaf(att[m], dc[m * NV + il], acc);
            out[(size_t)r * NN + tid] = acc;
        }
        __syncthreads();   // dc + ring stage fully consumed before refill/reuse
    }
}

extern "C" void kernel_launch(void* const* d_in, const int* in_sizes, int n_in,
                              void* d_out, int out_size) {
    const float* flow = (const float*)d_in[0];   // (B, N, N, T) fp32
    const int*   adj  = (const int*)  d_in[1];   // (N, N) int32
    const float* W    = (const float*)d_in[2];   // (N, N, N) fp32
    float*       out  = (float*)d_out;           // (B, N, N, 1) fp32

    const int B = in_sizes[0] / ROWLEN;

    static int attr_set = 0;
    if (!attr_set) {
        cudaFuncSetAttribute(gat_kernel,
                             cudaFuncAttributeMaxDynamicSharedMemorySize,
                             SMEM_BYTES);
        attr_set = 1;
    }
    gat_kernel<<<NBLOCKS, NTHREADS, SMEM_BYTES>>>(flow, adj, W, out, B);
}